// round 16
// baseline (speedup 1.0000x reference)
#include <cuda_runtime.h>
#include <cuda_fp16.h>
#include <math.h>

#define BB     64
#define ICAPS  2048
#define KDIM   8
#define NCAPS  32
#define DDIM   16
#define JD     512           // NCAPS*DDIM
#define SP_C   0.5413248546129181f
#define IPB    2             // i per pass0 block (1024 blocks)

typedef unsigned long long ull;

// ---- device scratch (no allocations allowed) ----
__device__ __half g_uhat[(size_t)BB * ICAPS * JD];     // 134 MB fp16 predictions
__device__ float  g_s0[BB * JD];
__device__ float  g_s1[BB * JD];
__device__ float  g_s2[BB * JD];

__device__ __forceinline__ float softplusf(float z) {
    return z > 15.f ? z : __logf(1.f + __expf(z));
}
// ---- Blackwell packed f32x2 helpers (used in pass0 only) ----
__device__ __forceinline__ ull pk2(float lo, float hi) {
    ull d; asm("mov.b64 %0, {%1, %2};" : "=l"(d) : "f"(lo), "f"(hi)); return d;
}
__device__ __forceinline__ void upk2(float& lo, float& hi, ull v) {
    asm("mov.b64 {%0, %1}, %2;" : "=f"(lo), "=f"(hi) : "l"(v));
}
__device__ __forceinline__ ull mul2(ull a, ull b) {
    ull d; asm("mul.rn.f32x2 %0, %1, %2;" : "=l"(d) : "l"(a), "l"(b)); return d;
}
__device__ __forceinline__ ull fma2(ull a, ull b, ull c) {
    ull d; asm("fma.rn.f32x2 %0, %1, %2, %3;" : "=l"(d) : "l"(a), "l"(b), "l"(c)); return d;
}

// ---------------------------------------------------------------------------
// pass0 (R13-proven, verbatim): W = loc + (1e-5 + softplus(C+sraw))*eps;
//        u_hat[b,i,jd] = sum_k W[i,jd,k]*x[b,i,k] -> half2 store.
// f32x2 packed over BATCH PAIRS; x staged transposed as ull pairs x_s[k][bp].
// First 32 blocks also zero s0/s1/s2 (folded init).
// ---------------------------------------------------------------------------
__global__ void __launch_bounds__(256) pass0_kernel(
    const float* __restrict__ x, const float* __restrict__ loc,
    const float* __restrict__ sraw, const float* __restrict__ eps)
{
    __shared__ ull x_s[KDIM * (BB / 2)];   // [k][b-pair], 2 KB
    const int t = threadIdx.x;
    const int i0 = blockIdx.x * IPB;

    if (blockIdx.x < 32) {   // folded init: 1024 floats per block per array
        int base = blockIdx.x * 1024 + t;
        #pragma unroll
        for (int q = 0; q < 4; ++q) {
            int idx = base + q * 256;
            g_s0[idx] = 0.f; g_s1[idx] = 0.f; g_s2[idx] = 0.f;
        }
    }

    for (int ii = 0; ii < IPB; ++ii) {
        const int i = i0 + ii;
        const size_t wb = ((size_t)i * JD + 2 * t) * KDIM;
        float4 L[4], R[4], E[4];
        #pragma unroll
        for (int q = 0; q < 4; ++q) {
            L[q] = *(const float4*)(loc  + wb + 4 * q);
            R[q] = *(const float4*)(sraw + wb + 4 * q);
            E[q] = *(const float4*)(eps  + wb + 4 * q);
        }
        float W[16];    // [0..7]=jd even row k0..7, [8..15]=jd odd row
        #pragma unroll
        for (int q = 0; q < 4; ++q) {
            const float* l = (const float*)&L[q];
            const float* r = (const float*)&R[q];
            const float* e = (const float*)&E[q];
            #pragma unroll
            for (int u = 0; u < 4; ++u)
                W[4 * q + u] = l[u] + (1e-5f + softplusf(SP_C + r[u])) * e[u];
        }
        ull Wp0[KDIM], Wp1[KDIM];
        #pragma unroll
        for (int k = 0; k < KDIM; ++k) {
            Wp0[k] = pk2(W[k],     W[k]);
            Wp1[k] = pk2(W[8 + k], W[8 + k]);
        }

        __syncthreads();   // previous iter's b-loop readers done
        {   // transposed stage: x_s[k][bp] = (x[2bp,i,k], x[2bp+1,i,k])
            int m0 = t, m1 = t + 256;   // m = b*8 + k
            float v0 = x[((size_t)(m0 >> 3) * ICAPS + i) * KDIM + (m0 & 7)];
            float v1 = x[((size_t)(m1 >> 3) * ICAPS + i) * KDIM + (m1 & 7)];
            float* xs = (float*)x_s;
            xs[(m0 & 7) * BB + (m0 >> 3)] = v0;
            xs[(m1 & 7) * BB + (m1 >> 3)] = v1;
        }
        __syncthreads();

        __half2* up = (__half2*)g_uhat + (size_t)i * (JD / 2) + t;
        const size_t bstride = (size_t)ICAPS * (JD / 2);   // half2 units
        #pragma unroll 4
        for (int bp = 0; bp < BB / 2; ++bp) {
            ull acc0, acc1;
            {
                ull xp = x_s[0 * (BB / 2) + bp];
                acc0 = mul2(Wp0[0], xp);
                acc1 = mul2(Wp1[0], xp);
            }
            #pragma unroll
            for (int k = 1; k < KDIM; ++k) {
                ull xp = x_s[k * (BB / 2) + bp];
                acc0 = fma2(Wp0[k], xp, acc0);
                acc1 = fma2(Wp1[k], xp, acc1);
            }
            float u0b0, u0b1, u1b0, u1b1;
            upk2(u0b0, u0b1, acc0);   // jd even: (b=2bp, b=2bp+1)
            upk2(u1b0, u1b1, acc1);   // jd odd
            up[(size_t)(2 * bp)     * bstride] = __floats2half2_rn(u0b0, u1b0);
            up[(size_t)(2 * bp + 1) * bstride] = __floats2half2_rn(u0b1, u1b1);
        }
    }
}

// ---------------------------------------------------------------------------
// reduce_s0: s0[b,jd] = sum_i uhat[b,i,jd]. grid (BB,16), 256 thr — ONLY
// change vs R13: 1024 blocks (~7/SM residency vs 3.5) for this latency-bound
// L2-read loop. uint4 loads, 8 accumulators, i descending.
// ---------------------------------------------------------------------------
__global__ void __launch_bounds__(256) reduce_s0_kernel() {
    const int b = blockIdx.x, ch = blockIdx.y, t = threadIdx.x;
    const int o = t & 63, r = t >> 6;
    const uint4* base = (const uint4*)(g_uhat + (size_t)b * ICAPS * JD) + o;
    const int i_hi = (ch + 1) * (ICAPS / 16) - 1 - r;   // 128-i chunk, step -4
    float acc[8];
    #pragma unroll
    for (int q = 0; q < 8; ++q) acc[q] = 0.f;
    #pragma unroll 4
    for (int s = 0; s < ICAPS / 64; ++s) {              // 32 iters
        uint4 p = base[(size_t)(i_hi - 4 * s) * (JD / 8)];
        const __half2* h = (const __half2*)&p;
        #pragma unroll
        for (int q = 0; q < 4; ++q) {
            float2 f = __half22float2(h[q]);
            acc[2 * q]     += f.x;
            acc[2 * q + 1] += f.y;
        }
    }
    float* dst = g_s0 + b * JD + 8 * o;
    #pragma unroll
    for (int q = 0; q < 8; ++q) atomicAdd(dst + q, acc[q]);
}

// ---------------------------------------------------------------------------
// route pass (R3/R8-proven, FROZEN).
//   !LAST: v = squash(s0/32)              -> accumulates s1
//    LAST: v = squash(s0/32) + squash(s1) -> accumulates s2, writes c
// ---------------------------------------------------------------------------
template<bool LAST>
__global__ void __launch_bounds__(128) route_kernel(float* __restrict__ c_out)
{
    __shared__ float v_s[JD];
    __shared__ float sp_s[4][NCAPS * 17 + 1];
    const int b = blockIdx.x;
    const int tid = threadIdx.x, lane = tid & 31, w = tid >> 5;

    if (tid < NCAPS) {
        float tv[DDIM]; float n = 0.f;
        const float4* s4 = (const float4*)(g_s0 + ((size_t)b * NCAPS + tid) * DDIM);
        #pragma unroll
        for (int q = 0; q < 4; ++q) {
            float4 p = s4[q];
            tv[4*q+0] = p.x * (1.f/NCAPS); tv[4*q+1] = p.y * (1.f/NCAPS);
            tv[4*q+2] = p.z * (1.f/NCAPS); tv[4*q+3] = p.w * (1.f/NCAPS);
        }
        #pragma unroll
        for (int d = 0; d < DDIM; ++d) n = fmaf(tv[d], tv[d], n);
        float sc = n / ((1.f + n) * sqrtf(n + 1e-7f));
        float vout[DDIM];
        #pragma unroll
        for (int d = 0; d < DDIM; ++d) vout[d] = tv[d] * sc;
        if (LAST) {
            float t1[DDIM]; float n1 = 0.f;
            const float4* s14 = (const float4*)(g_s1 + ((size_t)b * NCAPS + tid) * DDIM);
            #pragma unroll
            for (int q = 0; q < 4; ++q) {
                float4 p = s14[q];
                t1[4*q+0] = p.x; t1[4*q+1] = p.y; t1[4*q+2] = p.z; t1[4*q+3] = p.w;
            }
            #pragma unroll
            for (int d = 0; d < DDIM; ++d) n1 = fmaf(t1[d], t1[d], n1);
            float sc1 = n1 / ((1.f + n1) * sqrtf(n1 + 1e-7f));
            #pragma unroll
            for (int d = 0; d < DDIM; ++d) vout[d] += t1[d] * sc1;
        }
        #pragma unroll
        for (int d = 0; d < DDIM; ++d) v_s[tid * DDIM + d] = vout[d];
    }
    __syncthreads();

    float v[DDIM];
    {
        const float4* v4 = (const float4*)(v_s + lane * DDIM);
        #pragma unroll
        for (int q = 0; q < 4; ++q) {
            float4 p = v4[q];
            v[4*q+0] = p.x; v[4*q+1] = p.y; v[4*q+2] = p.z; v[4*q+3] = p.w;
        }
    }
    float sp[DDIM];
    #pragma unroll
    for (int d = 0; d < DDIM; ++d) sp[d] = 0.f;

    const int per_block = ICAPS / 16;          // 128
    const int per_warp  = per_block / 4;       // 32
    const int ibase = blockIdx.y * per_block + w * per_warp;
    const __half2* ubase = (const __half2*)g_uhat
                         + (size_t)b * ICAPS * (JD/2) + lane * (DDIM/2);

    for (int it = 0; it < per_warp / 4; ++it) {
        const int i = ibase + it * 4;
        uint4 ua[4], ub[4];
        #pragma unroll
        for (int r = 0; r < 4; ++r) {
            const uint4* p = (const uint4*)(ubase + (size_t)(i + r) * (JD/2));
            ua[r] = p[0]; ub[r] = p[1];
        }
        float ev[4];
        #pragma unroll
        for (int r = 0; r < 4; ++r) {
            float bl = 0.f;
            const __half2* ha = (const __half2*)&ua[r];
            const __half2* hb = (const __half2*)&ub[r];
            #pragma unroll
            for (int q = 0; q < 4; ++q) {
                float2 f = __half22float2(ha[q]);
                bl = fmaf(f.x, v[2*q],   fmaf(f.y, v[2*q+1],   bl));
            }
            #pragma unroll
            for (int q = 0; q < 4; ++q) {
                float2 f = __half22float2(hb[q]);
                bl = fmaf(f.x, v[8+2*q], fmaf(f.y, v[8+2*q+1], bl));
            }
            ev[r] = __expf(bl);   // logits bounded: no max-subtraction needed
        }
        float t0 = ev[0], t1 = ev[1], t2 = ev[2], t3 = ev[3];
        #pragma unroll
        for (int off = 16; off; off >>= 1) {   // 4 interleaved butterflies
            t0 += __shfl_xor_sync(0xffffffffu, t0, off);
            t1 += __shfl_xor_sync(0xffffffffu, t1, off);
            t2 += __shfl_xor_sync(0xffffffffu, t2, off);
            t3 += __shfl_xor_sync(0xffffffffu, t3, off);
        }
        float sums[4] = {t0, t1, t2, t3};
        #pragma unroll
        for (int r = 0; r < 4; ++r) {
            float c = __fdividef(ev[r], sums[r]);
            const __half2* ha = (const __half2*)&ua[r];
            const __half2* hb = (const __half2*)&ub[r];
            #pragma unroll
            for (int q = 0; q < 4; ++q) {
                float2 f = __half22float2(ha[q]);
                sp[2*q]     = fmaf(c, f.x, sp[2*q]);
                sp[2*q+1]   = fmaf(c, f.y, sp[2*q+1]);
            }
            #pragma unroll
            for (int q = 0; q < 4; ++q) {
                float2 f = __half22float2(hb[q]);
                sp[8+2*q]   = fmaf(c, f.x, sp[8+2*q]);
                sp[8+2*q+1] = fmaf(c, f.y, sp[8+2*q+1]);
            }
            if (LAST)
                c_out[((size_t)b * ICAPS + i + r) * NCAPS + lane] = c;
        }
    }
    // cross-warp reduce in smem, then one REDG burst
    #pragma unroll
    for (int d = 0; d < DDIM; ++d) sp_s[w][lane * 17 + d] = sp[d];
    __syncthreads();
    float* s_out = (LAST ? g_s2 : g_s1) + (size_t)b * JD;
    #pragma unroll
    for (int q = 0; q < 4; ++q) {
        int idx = tid * 4 + q;          // 0..511
        int j = idx >> 4, d = idx & 15;
        float a = sp_s[0][j*17+d] + sp_s[1][j*17+d]
                + sp_s[2][j*17+d] + sp_s[3][j*17+d];
        atomicAdd(s_out + idx, a);
    }
}

// ---------------------------------------------------------------------------
__global__ void squash_final_kernel(float* __restrict__ out_v)
{
    int idx = blockIdx.x * blockDim.x + threadIdx.x;
    if (idx >= BB * NCAPS) return;
    float s[DDIM]; float n = 0.f;
    const float4* s4 = (const float4*)(g_s2 + (size_t)idx * DDIM);
    #pragma unroll
    for (int q = 0; q < 4; ++q) {
        float4 p = s4[q];
        s[4*q+0] = p.x; s[4*q+1] = p.y; s[4*q+2] = p.z; s[4*q+3] = p.w;
    }
    #pragma unroll
    for (int d = 0; d < DDIM; ++d) n = fmaf(s[d], s[d], n);
    float sc = n / ((1.f + n) * sqrtf(n + 1e-7f));
    float4* d4 = (float4*)(out_v + (size_t)idx * DDIM);
    #pragma unroll
    for (int q = 0; q < 4; ++q) {
        float4 o;
        o.x = s[4*q+0] * sc; o.y = s[4*q+1] * sc;
        o.z = s[4*q+2] * sc; o.w = s[4*q+3] * sc;
        d4[q] = o;
    }
}

// ---------------------------------------------------------------------------
extern "C" void kernel_launch(void* const* d_in, const int* in_sizes, int n_in,
                              void* d_out, int out_size)
{
    const float* x    = (const float*)d_in[0];
    const float* loc  = (const float*)d_in[1];
    const float* sraw = (const float*)d_in[2];
    const float* eps  = (const float*)d_in[3];
    float* out_v = (float*)d_out;                 // [B, NCAPS, DDIM]
    float* out_c = out_v + BB * NCAPS * DDIM;     // [B, ICAPS, NCAPS]

    pass0_kernel<<<ICAPS / IPB, 256>>>(x, loc, sraw, eps);   // 1024 blocks
    reduce_s0_kernel<<<dim3(BB, 16), 256>>>();               // 1024 blocks
    route_kernel<false><<<dim3(BB, 16), 128>>>(nullptr);     // iter 1 -> s1
    route_kernel<true><<<dim3(BB, 16), 128>>>(out_c);        // iter 2 -> s2, c
    squash_final_kernel<<<(BB * NCAPS + 63) / 64, 64>>>(out_v);
}

// round 17
// speedup vs baseline: 1.0294x; 1.0294x over previous
#include <cuda_runtime.h>
#include <cuda_fp16.h>
#include <math.h>

#define BB     64
#define ICAPS  2048
#define KDIM   8
#define NCAPS  32
#define DDIM   16
#define JD     512           // NCAPS*DDIM
#define SP_C   0.5413248546129181f
#define IPB    2             // i per pass0 block (1024 blocks)

typedef unsigned long long ull;

// ---- device scratch (no allocations allowed) ----
__device__ __half g_uhat[(size_t)BB * ICAPS * JD];     // 134 MB fp16 predictions
__device__ float  g_s0[BB * JD];
__device__ float  g_s1[BB * JD];
__device__ float  g_s2[BB * JD];

__device__ __forceinline__ float softplusf(float z) {
    return z > 15.f ? z : __logf(1.f + __expf(z));
}
// ---- Blackwell packed f32x2 helpers (used in pass0 only) ----
__device__ __forceinline__ ull pk2(float lo, float hi) {
    ull d; asm("mov.b64 %0, {%1, %2};" : "=l"(d) : "f"(lo), "f"(hi)); return d;
}
__device__ __forceinline__ void upk2(float& lo, float& hi, ull v) {
    asm("mov.b64 {%0, %1}, %2;" : "=f"(lo), "=f"(hi) : "l"(v));
}
__device__ __forceinline__ ull mul2(ull a, ull b) {
    ull d; asm("mul.rn.f32x2 %0, %1, %2;" : "=l"(d) : "l"(a), "l"(b)); return d;
}
__device__ __forceinline__ ull fma2(ull a, ull b, ull c) {
    ull d; asm("fma.rn.f32x2 %0, %1, %2, %3;" : "=l"(d) : "l"(a), "l"(b), "l"(c)); return d;
}

// ---------------------------------------------------------------------------
// pass0 (R13 champion, verbatim): W = loc + (1e-5 + softplus(C+sraw))*eps;
//        u_hat[b,i,jd] = sum_k W[i,jd,k]*x[b,i,k] -> half2 store.
// f32x2 packed over BATCH PAIRS; x staged transposed as ull pairs x_s[k][bp].
// First 32 blocks also zero s0/s1/s2 (folded init).
// ---------------------------------------------------------------------------
__global__ void __launch_bounds__(256) pass0_kernel(
    const float* __restrict__ x, const float* __restrict__ loc,
    const float* __restrict__ sraw, const float* __restrict__ eps)
{
    __shared__ ull x_s[KDIM * (BB / 2)];   // [k][b-pair], 2 KB
    const int t = threadIdx.x;
    const int i0 = blockIdx.x * IPB;

    if (blockIdx.x < 32) {   // folded init: 1024 floats per block per array
        int base = blockIdx.x * 1024 + t;
        #pragma unroll
        for (int q = 0; q < 4; ++q) {
            int idx = base + q * 256;
            g_s0[idx] = 0.f; g_s1[idx] = 0.f; g_s2[idx] = 0.f;
        }
    }

    for (int ii = 0; ii < IPB; ++ii) {
        const int i = i0 + ii;
        const size_t wb = ((size_t)i * JD + 2 * t) * KDIM;
        float4 L[4], R[4], E[4];
        #pragma unroll
        for (int q = 0; q < 4; ++q) {
            L[q] = *(const float4*)(loc  + wb + 4 * q);
            R[q] = *(const float4*)(sraw + wb + 4 * q);
            E[q] = *(const float4*)(eps  + wb + 4 * q);
        }
        float W[16];    // [0..7]=jd even row k0..7, [8..15]=jd odd row
        #pragma unroll
        for (int q = 0; q < 4; ++q) {
            const float* l = (const float*)&L[q];
            const float* r = (const float*)&R[q];
            const float* e = (const float*)&E[q];
            #pragma unroll
            for (int u = 0; u < 4; ++u)
                W[4 * q + u] = l[u] + (1e-5f + softplusf(SP_C + r[u])) * e[u];
        }
        ull Wp0[KDIM], Wp1[KDIM];
        #pragma unroll
        for (int k = 0; k < KDIM; ++k) {
            Wp0[k] = pk2(W[k],     W[k]);
            Wp1[k] = pk2(W[8 + k], W[8 + k]);
        }

        __syncthreads();   // previous iter's b-loop readers done
        {   // transposed stage: x_s[k][bp] = (x[2bp,i,k], x[2bp+1,i,k])
            int m0 = t, m1 = t + 256;   // m = b*8 + k
            float v0 = x[((size_t)(m0 >> 3) * ICAPS + i) * KDIM + (m0 & 7)];
            float v1 = x[((size_t)(m1 >> 3) * ICAPS + i) * KDIM + (m1 & 7)];
            float* xs = (float*)x_s;
            xs[(m0 & 7) * BB + (m0 >> 3)] = v0;
            xs[(m1 & 7) * BB + (m1 >> 3)] = v1;
        }
        __syncthreads();

        __half2* up = (__half2*)g_uhat + (size_t)i * (JD / 2) + t;
        const size_t bstride = (size_t)ICAPS * (JD / 2);   // half2 units
        #pragma unroll 4
        for (int bp = 0; bp < BB / 2; ++bp) {
            ull acc0, acc1;
            {
                ull xp = x_s[0 * (BB / 2) + bp];
                acc0 = mul2(Wp0[0], xp);
                acc1 = mul2(Wp1[0], xp);
            }
            #pragma unroll
            for (int k = 1; k < KDIM; ++k) {
                ull xp = x_s[k * (BB / 2) + bp];
                acc0 = fma2(Wp0[k], xp, acc0);
                acc1 = fma2(Wp1[k], xp, acc1);
            }
            float u0b0, u0b1, u1b0, u1b1;
            upk2(u0b0, u0b1, acc0);   // jd even: (b=2bp, b=2bp+1)
            upk2(u1b0, u1b1, acc1);   // jd odd
            up[(size_t)(2 * bp)     * bstride] = __floats2half2_rn(u0b0, u1b0);
            up[(size_t)(2 * bp + 1) * bstride] = __floats2half2_rn(u0b1, u1b1);
        }
    }
}

// ---------------------------------------------------------------------------
// reduce_s0 (R13 champion): s0[b,jd] = sum_i uhat[b,i,jd]. grid (BB,8),
// 256 thr. uint4 loads, 8 accumulators, i descending for pass0 L2 hits.
// ---------------------------------------------------------------------------
__global__ void __launch_bounds__(256) reduce_s0_kernel() {
    const int b = blockIdx.x, ch = blockIdx.y, t = threadIdx.x;
    const int o = t & 63, r = t >> 6;
    const uint4* base = (const uint4*)(g_uhat + (size_t)b * ICAPS * JD) + o;
    const int i_hi = (ch + 1) * (ICAPS / 8) - 1 - r;    // step -4
    float acc[8];
    #pragma unroll
    for (int q = 0; q < 8; ++q) acc[q] = 0.f;
    #pragma unroll 4
    for (int s = 0; s < ICAPS / 32; ++s) {              // 64 iters
        uint4 p = base[(size_t)(i_hi - 4 * s) * (JD / 8)];
        const __half2* h = (const __half2*)&p;
        #pragma unroll
        for (int q = 0; q < 4; ++q) {
            float2 f = __half22float2(h[q]);
            acc[2 * q]     += f.x;
            acc[2 * q + 1] += f.y;
        }
    }
    float* dst = g_s0 + b * JD + 8 * o;
    #pragma unroll
    for (int q = 0; q < 8; ++q) atomicAdd(dst + q, acc[q]);
}

// ---------------------------------------------------------------------------
// route pass (R3/R8-proven, FROZEN).
//   !LAST: v = squash(s0/32)              -> accumulates s1
//    LAST: v = squash(s0/32) + squash(s1) -> accumulates s2, writes c
// ---------------------------------------------------------------------------
template<bool LAST>
__global__ void __launch_bounds__(128) route_kernel(float* __restrict__ c_out)
{
    __shared__ float v_s[JD];
    __shared__ float sp_s[4][NCAPS * 17 + 1];
    const int b = blockIdx.x;
    const int tid = threadIdx.x, lane = tid & 31, w = tid >> 5;

    if (tid < NCAPS) {
        float tv[DDIM]; float n = 0.f;
        const float4* s4 = (const float4*)(g_s0 + ((size_t)b * NCAPS + tid) * DDIM);
        #pragma unroll
        for (int q = 0; q < 4; ++q) {
            float4 p = s4[q];
            tv[4*q+0] = p.x * (1.f/NCAPS); tv[4*q+1] = p.y * (1.f/NCAPS);
            tv[4*q+2] = p.z * (1.f/NCAPS); tv[4*q+3] = p.w * (1.f/NCAPS);
        }
        #pragma unroll
        for (int d = 0; d < DDIM; ++d) n = fmaf(tv[d], tv[d], n);
        float sc = n / ((1.f + n) * sqrtf(n + 1e-7f));
        float vout[DDIM];
        #pragma unroll
        for (int d = 0; d < DDIM; ++d) vout[d] = tv[d] * sc;
        if (LAST) {
            float t1[DDIM]; float n1 = 0.f;
            const float4* s14 = (const float4*)(g_s1 + ((size_t)b * NCAPS + tid) * DDIM);
            #pragma unroll
            for (int q = 0; q < 4; ++q) {
                float4 p = s14[q];
                t1[4*q+0] = p.x; t1[4*q+1] = p.y; t1[4*q+2] = p.z; t1[4*q+3] = p.w;
            }
            #pragma unroll
            for (int d = 0; d < DDIM; ++d) n1 = fmaf(t1[d], t1[d], n1);
            float sc1 = n1 / ((1.f + n1) * sqrtf(n1 + 1e-7f));
            #pragma unroll
            for (int d = 0; d < DDIM; ++d) vout[d] += t1[d] * sc1;
        }
        #pragma unroll
        for (int d = 0; d < DDIM; ++d) v_s[tid * DDIM + d] = vout[d];
    }
    __syncthreads();

    float v[DDIM];
    {
        const float4* v4 = (const float4*)(v_s + lane * DDIM);
        #pragma unroll
        for (int q = 0; q < 4; ++q) {
            float4 p = v4[q];
            v[4*q+0] = p.x; v[4*q+1] = p.y; v[4*q+2] = p.z; v[4*q+3] = p.w;
        }
    }
    float sp[DDIM];
    #pragma unroll
    for (int d = 0; d < DDIM; ++d) sp[d] = 0.f;

    const int per_block = ICAPS / 16;          // 128
    const int per_warp  = per_block / 4;       // 32
    const int ibase = blockIdx.y * per_block + w * per_warp;
    const __half2* ubase = (const __half2*)g_uhat
                         + (size_t)b * ICAPS * (JD/2) + lane * (DDIM/2);

    for (int it = 0; it < per_warp / 4; ++it) {
        const int i = ibase + it * 4;
        uint4 ua[4], ub[4];
        #pragma unroll
        for (int r = 0; r < 4; ++r) {
            const uint4* p = (const uint4*)(ubase + (size_t)(i + r) * (JD/2));
            ua[r] = p[0]; ub[r] = p[1];
        }
        float ev[4];
        #pragma unroll
        for (int r = 0; r < 4; ++r) {
            float bl = 0.f;
            const __half2* ha = (const __half2*)&ua[r];
            const __half2* hb = (const __half2*)&ub[r];
            #pragma unroll
            for (int q = 0; q < 4; ++q) {
                float2 f = __half22float2(ha[q]);
                bl = fmaf(f.x, v[2*q],   fmaf(f.y, v[2*q+1],   bl));
            }
            #pragma unroll
            for (int q = 0; q < 4; ++q) {
                float2 f = __half22float2(hb[q]);
                bl = fmaf(f.x, v[8+2*q], fmaf(f.y, v[8+2*q+1], bl));
            }
            ev[r] = __expf(bl);   // logits bounded: no max-subtraction needed
        }
        float t0 = ev[0], t1 = ev[1], t2 = ev[2], t3 = ev[3];
        #pragma unroll
        for (int off = 16; off; off >>= 1) {   // 4 interleaved butterflies
            t0 += __shfl_xor_sync(0xffffffffu, t0, off);
            t1 += __shfl_xor_sync(0xffffffffu, t1, off);
            t2 += __shfl_xor_sync(0xffffffffu, t2, off);
            t3 += __shfl_xor_sync(0xffffffffu, t3, off);
        }
        float sums[4] = {t0, t1, t2, t3};
        #pragma unroll
        for (int r = 0; r < 4; ++r) {
            float c = __fdividef(ev[r], sums[r]);
            const __half2* ha = (const __half2*)&ua[r];
            const __half2* hb = (const __half2*)&ub[r];
            #pragma unroll
            for (int q = 0; q < 4; ++q) {
                float2 f = __half22float2(ha[q]);
                sp[2*q]     = fmaf(c, f.x, sp[2*q]);
                sp[2*q+1]   = fmaf(c, f.y, sp[2*q+1]);
            }
            #pragma unroll
            for (int q = 0; q < 4; ++q) {
                float2 f = __half22float2(hb[q]);
                sp[8+2*q]   = fmaf(c, f.x, sp[8+2*q]);
                sp[8+2*q+1] = fmaf(c, f.y, sp[8+2*q+1]);
            }
            if (LAST)
                c_out[((size_t)b * ICAPS + i + r) * NCAPS + lane] = c;
        }
    }
    // cross-warp reduce in smem, then one REDG burst
    #pragma unroll
    for (int d = 0; d < DDIM; ++d) sp_s[w][lane * 17 + d] = sp[d];
    __syncthreads();
    float* s_out = (LAST ? g_s2 : g_s1) + (size_t)b * JD;
    #pragma unroll
    for (int q = 0; q < 4; ++q) {
        int idx = tid * 4 + q;          // 0..511
        int j = idx >> 4, d = idx & 15;
        float a = sp_s[0][j*17+d] + sp_s[1][j*17+d]
                + sp_s[2][j*17+d] + sp_s[3][j*17+d];
        atomicAdd(s_out + idx, a);
    }
}

// ---------------------------------------------------------------------------
__global__ void squash_final_kernel(float* __restrict__ out_v)
{
    int idx = blockIdx.x * blockDim.x + threadIdx.x;
    if (idx >= BB * NCAPS) return;
    float s[DDIM]; float n = 0.f;
    const float4* s4 = (const float4*)(g_s2 + (size_t)idx * DDIM);
    #pragma unroll
    for (int q = 0; q < 4; ++q) {
        float4 p = s4[q];
        s[4*q+0] = p.x; s[4*q+1] = p.y; s[4*q+2] = p.z; s[4*q+3] = p.w;
    }
    #pragma unroll
    for (int d = 0; d < DDIM; ++d) n = fmaf(s[d], s[d], n);
    float sc = n / ((1.f + n) * sqrtf(n + 1e-7f));
    float4* d4 = (float4*)(out_v + (size_t)idx * DDIM);
    #pragma unroll
    for (int q = 0; q < 4; ++q) {
        float4 o;
        o.x = s[4*q+0] * sc; o.y = s[4*q+1] * sc;
        o.z = s[4*q+2] * sc; o.w = s[4*q+3] * sc;
        d4[q] = o;
    }
}

// ---------------------------------------------------------------------------
extern "C" void kernel_launch(void* const* d_in, const int* in_sizes, int n_in,
                              void* d_out, int out_size)
{
    const float* x    = (const float*)d_in[0];
    const float* loc  = (const float*)d_in[1];
    const float* sraw = (const float*)d_in[2];
    const float* eps  = (const float*)d_in[3];
    float* out_v = (float*)d_out;                 // [B, NCAPS, DDIM]
    float* out_c = out_v + BB * NCAPS * DDIM;     // [B, ICAPS, NCAPS]

    pass0_kernel<<<ICAPS / IPB, 256>>>(x, loc, sraw, eps);   // 1024 blocks
    reduce_s0_kernel<<<dim3(BB, 8), 256>>>();                // 512 blocks
    route_kernel<false><<<dim3(BB, 16), 128>>>(nullptr);     // iter 1 -> s1
    route_kernel<true><<<dim3(BB, 16), 128>>>(out_c);        // iter 2 -> s2, c
    squash_final_kernel<<<(BB * NCAPS + 63) / 64, 64>>>(out_v);
}